// round 15
// baseline (speedup 1.0000x reference)
#include <cuda_runtime.h>

#define G        64
#define IMGSZ    512
#define CHSTRIDE (IMGSZ * IMGSZ)
#define NTHREADS 512

#define EDGE_SCALE (1.0f / 0.875f)   // all patch-edge wsums are 7/8

// S=4 tmp: [3][8][264]; col j at +2; pads {0,1,258,259}=0. Row = 66 float4s.
// S=2 tmp: [3][16][132]; col j at +1; pads {0,129}=0. Row = 66 float2s.

__device__ __forceinline__ float2 ldg2(const float* p) { return __ldg((const float2*)p); }

// ---------------- S = 4 scalar phase 1 (odd bx) — R14 path ----------------
__device__ void ds4_phase1_scalar(const float* __restrict__ imgb,
                                  int by, int bx, int y0, float* __restrict__ tmp) {
    const int tid = threadIdx.x;
    const int j   = tid & 255;
    const int h   = tid >> 8;          // 0..1
    const int ylo = y0 + 4 * h;
    const int gx  = bx + j;
    float* tb = tmp + (4 * h) * 264 + 2 + j;
    if ((unsigned)gx >= (unsigned)IMGSZ) {
#pragma unroll
        for (int ch = 0; ch < 3; ch++)
#pragma unroll
            for (int yy = 0; yy < 4; yy++) tb[ch * 2112 + yy * 264] = 0.f;
        return;
    }
    const int rlo = 4 * ylo - 2;
    const bool allok = (rlo >= 0) && (rlo + 19 < 256) &&
                       (by + rlo >= 0) && (by + rlo + 19 < IMGSZ);
    float sp[3] = {0.f, 0.f, 0.f};
    if (allok) {
        const float* p = imgb + (size_t)(by + rlo) * IMGSZ + gx;
#pragma unroll
        for (int cm = 0; cm <= 4; cm++) {
#pragma unroll
            for (int ch = 0; ch < 3; ch++) {
                const float* q = p + ch * CHSTRIDE + 4 * cm * IMGSZ;
                float v0 = __ldg(q);
                float v1 = __ldg(q + IMGSZ);
                float v2 = __ldg(q + 2 * IMGSZ);
                float v3 = __ldg(q + 3 * IMGSZ);
                float s = fmaf(7.f/32, v3, fmaf(5.f/32, v2, fmaf(3.f/32, v1, (1.f/32)*v0)));
                float t = fmaf(1.f/32, v3, fmaf(3.f/32, v2, fmaf(5.f/32, v1, (7.f/32)*v0)));
                if (cm > 0) {
                    int y = ylo + cm - 1;
                    float r = sp[ch] + t;
                    if (y == 0 || y == 63) r *= EDGE_SCALE;
                    tb[ch * 2112 + (cm - 1) * 264] = r;
                }
                sp[ch] = s;
            }
        }
    } else {
#pragma unroll
        for (int cm = 0; cm <= 4; cm++) {
            float v[3][4];
#pragma unroll
            for (int k = 0; k < 4; k++) {
                int r  = 4 * (ylo + cm) - 2 + k;
                int gy = by + r;
                bool ok = (unsigned)r < 256u && (unsigned)gy < (unsigned)IMGSZ;
                const float* q = imgb + (size_t)(ok ? gy : 0) * IMGSZ + gx;
#pragma unroll
                for (int ch = 0; ch < 3; ch++)
                    v[ch][k] = ok ? __ldg(q + ch * CHSTRIDE) : 0.f;
            }
#pragma unroll
            for (int ch = 0; ch < 3; ch++) {
                float s = fmaf(7.f/32, v[ch][3], fmaf(5.f/32, v[ch][2], fmaf(3.f/32, v[ch][1], (1.f/32)*v[ch][0])));
                float t = fmaf(1.f/32, v[ch][3], fmaf(3.f/32, v[ch][2], fmaf(5.f/32, v[ch][1], (7.f/32)*v[ch][0])));
                if (cm > 0) {
                    int y = ylo + cm - 1;
                    float r = sp[ch] + t;
                    if (y == 0 || y == 63) r *= EDGE_SCALE;
                    tb[ch * 2112 + (cm - 1) * 264] = r;
                }
                sp[ch] = s;
            }
        }
    }
}

// ---------------- S = 4 vector phase 1 (even bx): LDG.64 column pairs ------
// 512 threads = 128 pairs x 4 row-quarters (2 output rows, 3 chunks, 12 rows).
__device__ void ds4_phase1_vec(const float* __restrict__ imgb,
                               int by, int bx, int y0, float* __restrict__ tmp) {
    const int tid = threadIdx.x;
    const int u   = tid & 127;
    const int qq  = tid >> 7;          // 0..3
    const int ylo = y0 + 2 * qq;
    const int cb  = bx + 2 * u;        // even
    const int jb  = 2 * u;
    float* tb = tmp + (2 * qq) * 264 + 2 + jb;
    const int rlo = 4 * ylo - 2;

    if (cb >= 0 && cb + 1 < IMGSZ &&
        rlo >= 0 && rlo + 11 < 256 && by + rlo >= 0 && by + rlo + 11 < IMGSZ) {
        const float* p = imgb + (size_t)(by + rlo) * IMGSZ + cb;
        float2 sp[3];
#pragma unroll
        for (int ch = 0; ch < 3; ch++) sp[ch] = make_float2(0.f, 0.f);
#pragma unroll
        for (int cm = 0; cm <= 2; cm++) {
#pragma unroll
            for (int ch = 0; ch < 3; ch++) {
                const float* q = p + ch * CHSTRIDE + 4 * cm * IMGSZ;
                float2 v0 = ldg2(q);
                float2 v1 = ldg2(q + IMGSZ);
                float2 v2 = ldg2(q + 2 * IMGSZ);
                float2 v3 = ldg2(q + 3 * IMGSZ);
                float2 s, t;
                s.x = fmaf(7.f/32, v3.x, fmaf(5.f/32, v2.x, fmaf(3.f/32, v1.x, (1.f/32)*v0.x)));
                s.y = fmaf(7.f/32, v3.y, fmaf(5.f/32, v2.y, fmaf(3.f/32, v1.y, (1.f/32)*v0.y)));
                t.x = fmaf(1.f/32, v3.x, fmaf(3.f/32, v2.x, fmaf(5.f/32, v1.x, (7.f/32)*v0.x)));
                t.y = fmaf(1.f/32, v3.y, fmaf(3.f/32, v2.y, fmaf(5.f/32, v1.y, (7.f/32)*v0.y)));
                if (cm > 0) {
                    int y = ylo + cm - 1;
                    float es = (y == 0 || y == 63) ? EDGE_SCALE : 1.0f;
                    float2 r = make_float2((sp[ch].x + t.x) * es, (sp[ch].y + t.y) * es);
                    *(float2*)(tb + ch * 2112 + (cm - 1) * 264) = r;
                }
                sp[ch] = s;
            }
        }
    } else {
        // boundary: per-column scalar with full checks (j always in [0,255])
#pragma unroll
        for (int k = 0; k < 2; k++) {
            int c = cb + k;
            float* tk = tb + k;
            if ((unsigned)c >= (unsigned)IMGSZ) {
#pragma unroll
                for (int ch = 0; ch < 3; ch++)
#pragma unroll
                    for (int cm = 1; cm <= 2; cm++) tk[ch * 2112 + (cm - 1) * 264] = 0.f;
                continue;
            }
            float sp[3] = {0.f, 0.f, 0.f};
#pragma unroll
            for (int cm = 0; cm <= 2; cm++) {
                float v[3][4];
#pragma unroll
                for (int kk = 0; kk < 4; kk++) {
                    int r  = rlo + 4 * cm + kk;
                    int gy = by + r;
                    bool ok = (unsigned)r < 256u && (unsigned)gy < (unsigned)IMGSZ;
                    const float* q = imgb + (size_t)(ok ? gy : 0) * IMGSZ + c;
#pragma unroll
                    for (int ch = 0; ch < 3; ch++)
                        v[ch][kk] = ok ? __ldg(q + ch * CHSTRIDE) : 0.f;
                }
#pragma unroll
                for (int ch = 0; ch < 3; ch++) {
                    float s = fmaf(7.f/32, v[ch][3], fmaf(5.f/32, v[ch][2], fmaf(3.f/32, v[ch][1], (1.f/32)*v[ch][0])));
                    float t = fmaf(1.f/32, v[ch][3], fmaf(3.f/32, v[ch][2], fmaf(5.f/32, v[ch][1], (7.f/32)*v[ch][0])));
                    if (cm > 0) {
                        int y = ylo + cm - 1;
                        float es = (y == 0 || y == 63) ? EDGE_SCALE : 1.0f;
                        tk[ch * 2112 + (cm - 1) * 264] = (sp[ch] + t) * es;
                    }
                    sp[ch] = s;
                }
            }
        }
    }
}

// ---------------- S = 2 scalar phase 1 (odd bx) — R14 path ----------------
__device__ void ds2_phase1_scalar(const float* __restrict__ imgb,
                                  int by, int bx, int y0, float* __restrict__ tmp) {
    const int tid = threadIdx.x;
    const int j   = tid & 127;
    const int h   = tid >> 7;            // 0..3
    const int ylo = y0 + 4 * h;
    const int gx  = bx + j;
    float* tb = tmp + (4 * h) * 132 + 1 + j;
    if ((unsigned)gx >= (unsigned)IMGSZ) {
#pragma unroll
        for (int ch = 0; ch < 3; ch++)
#pragma unroll
            for (int yy = 0; yy < 4; yy++) tb[ch * 2112 + yy * 132] = 0.f;
        return;
    }
    const int rlo = 2 * ylo - 1;
    const bool allok = (rlo >= 0) && (rlo + 9 < 128) &&
                       (by + rlo >= 0) && (by + rlo + 9 < IMGSZ);
    float sp[3] = {0.f, 0.f, 0.f};
    if (allok) {
        const float* p = imgb + (size_t)(by + rlo) * IMGSZ + gx;
#pragma unroll
        for (int cm = 0; cm <= 4; cm++) {
#pragma unroll
            for (int ch = 0; ch < 3; ch++) {
                const float* q = p + ch * CHSTRIDE + 2 * cm * IMGSZ;
                float v0 = __ldg(q);
                float v1 = __ldg(q + IMGSZ);
                float s = fmaf(3.f/8, v1, (1.f/8)*v0);
                float t = fmaf(1.f/8, v1, (3.f/8)*v0);
                if (cm > 0) {
                    int y = ylo + cm - 1;
                    float r = sp[ch] + t;
                    if (y == 0 || y == 63) r *= EDGE_SCALE;
                    tb[ch * 2112 + (cm - 1) * 132] = r;
                }
                sp[ch] = s;
            }
        }
    } else {
#pragma unroll
        for (int cm = 0; cm <= 4; cm++) {
            float v[3][2];
#pragma unroll
            for (int k = 0; k < 2; k++) {
                int r  = 2 * (ylo + cm) - 1 + k;
                int gy = by + r;
                bool ok = (unsigned)r < 128u && (unsigned)gy < (unsigned)IMGSZ;
                const float* q = imgb + (size_t)(ok ? gy : 0) * IMGSZ + gx;
#pragma unroll
                for (int ch = 0; ch < 3; ch++)
                    v[ch][k] = ok ? __ldg(q + ch * CHSTRIDE) : 0.f;
            }
#pragma unroll
            for (int ch = 0; ch < 3; ch++) {
                float s = fmaf(3.f/8, v[ch][1], (1.f/8)*v[ch][0]);
                float t = fmaf(1.f/8, v[ch][1], (3.f/8)*v[ch][0]);
                if (cm > 0) {
                    int y = ylo + cm - 1;
                    float r = sp[ch] + t;
                    if (y == 0 || y == 63) r *= EDGE_SCALE;
                    tb[ch * 2112 + (cm - 1) * 132] = r;
                }
                sp[ch] = s;
            }
        }
    }
}

// ---------------- S = 2 vector phase 1 (even bx): LDG.64 column pairs ------
// 512 threads = 64 pairs x 8 row-eighths (2 output rows, 3 chunks, 6 rows).
__device__ void ds2_phase1_vec(const float* __restrict__ imgb,
                               int by, int bx, int y0, float* __restrict__ tmp) {
    const int tid = threadIdx.x;
    const int u   = tid & 63;
    const int ee  = tid >> 6;          // 0..7
    const int ylo = y0 + 2 * ee;
    const int cb  = bx + 2 * u;        // even
    const int jb  = 2 * u;
    float* tb = tmp + (2 * ee) * 132 + 1 + jb;
    const int rlo = 2 * ylo - 1;

    if (cb >= 0 && cb + 1 < IMGSZ &&
        rlo >= 0 && rlo + 5 < 128 && by + rlo >= 0 && by + rlo + 5 < IMGSZ) {
        const float* p = imgb + (size_t)(by + rlo) * IMGSZ + cb;
        float2 sp[3];
#pragma unroll
        for (int ch = 0; ch < 3; ch++) sp[ch] = make_float2(0.f, 0.f);
#pragma unroll
        for (int cm = 0; cm <= 2; cm++) {
#pragma unroll
            for (int ch = 0; ch < 3; ch++) {
                const float* q = p + ch * CHSTRIDE + 2 * cm * IMGSZ;
                float2 v0 = ldg2(q);
                float2 v1 = ldg2(q + IMGSZ);
                float2 s = make_float2(fmaf(3.f/8, v1.x, (1.f/8)*v0.x),
                                       fmaf(3.f/8, v1.y, (1.f/8)*v0.y));
                float2 t = make_float2(fmaf(1.f/8, v1.x, (3.f/8)*v0.x),
                                       fmaf(1.f/8, v1.y, (3.f/8)*v0.y));
                if (cm > 0) {
                    int y = ylo + cm - 1;
                    float es = (y == 0 || y == 63) ? EDGE_SCALE : 1.0f;
                    float* dst = tb + ch * 2112 + (cm - 1) * 132;
                    dst[0] = (sp[ch].x + t.x) * es;   // odd-aligned: 2 scalar STS
                    dst[1] = (sp[ch].y + t.y) * es;
                }
                sp[ch] = s;
            }
        }
    } else {
#pragma unroll
        for (int k = 0; k < 2; k++) {
            int c = cb + k;
            float* tk = tb + k;
            if ((unsigned)c >= (unsigned)IMGSZ) {
#pragma unroll
                for (int ch = 0; ch < 3; ch++)
#pragma unroll
                    for (int cm = 1; cm <= 2; cm++) tk[ch * 2112 + (cm - 1) * 132] = 0.f;
                continue;
            }
            float sp[3] = {0.f, 0.f, 0.f};
#pragma unroll
            for (int cm = 0; cm <= 2; cm++) {
                float v[3][2];
#pragma unroll
                for (int kk = 0; kk < 2; kk++) {
                    int r  = rlo + 2 * cm + kk;
                    int gy = by + r;
                    bool ok = (unsigned)r < 128u && (unsigned)gy < (unsigned)IMGSZ;
                    const float* q = imgb + (size_t)(ok ? gy : 0) * IMGSZ + c;
#pragma unroll
                    for (int ch = 0; ch < 3; ch++)
                        v[ch][kk] = ok ? __ldg(q + ch * CHSTRIDE) : 0.f;
                }
#pragma unroll
                for (int ch = 0; ch < 3; ch++) {
                    float s = fmaf(3.f/8, v[ch][1], (1.f/8)*v[ch][0]);
                    float t = fmaf(1.f/8, v[ch][1], (3.f/8)*v[ch][0]);
                    if (cm > 0) {
                        int y = ylo + cm - 1;
                        float es = (y == 0 || y == 63) ? EDGE_SCALE : 1.0f;
                        tk[ch * 2112 + (cm - 1) * 132] = (sp[ch] + t) * es;
                    }
                    sp[ch] = s;
                }
            }
        }
    }
}

// Grid (832 blocks), heavy work first:
//   [0, 512)   : S=4, 8 slices x 8 rows per b (3 channels fused)
//   [512, 768) : S=2, 4 slices x 16 rows per b
//   [768, 832) : direct 64x64 zero-padded crop of img0, 3 channels
__global__ __launch_bounds__(NTHREADS, 4)
void glimpse_kernel(const float* __restrict__ img0,
                    const float* __restrict__ img2,
                    const float* __restrict__ img4,
                    const float* __restrict__ loc,
                    float* __restrict__ out) {
    extern __shared__ __align__(16) float tmp[];

    int blk = blockIdx.x;
    int sel, b, slice;
    if (blk < 512)      { sel = 0; b = blk >> 3;         slice = blk & 7; }
    else if (blk < 768) { sel = 1; b = (blk - 512) >> 2; slice = (blk - 512) & 3; }
    else                { sel = 2; b = blk - 768;        slice = 0; }

    // start index, matching jnp: trunc(0.5f * ((loc + 1.0f) * 511.0f))
    float lx = loc[2 * b + 0];
    float ly = loc[2 * b + 1];
    int sx = (int)(0.5f * ((lx + 1.0f) * 511.0f));
    int sy = (int)(0.5f * ((ly + 1.0f) * 511.0f));

    const int tid = threadIdx.x;

    if (sel == 0) {
        const float* imgb = img4 + (size_t)b * 3 * CHSTRIDE;
        float* ob = out + (size_t)(b * 9 + 6) * (G * G);
        int by = sy - 128, bx = sx - 128, y0 = slice * 8;

        // zero pads: 24 rows (stride 264) x {0,1,258,259}
        if (tid < 96) {
            int rs = tid >> 2, k = tid & 3;
            tmp[rs * 264 + ((k < 2) ? k : 256 + k)] = 0.f;
        }
        if ((bx & 1) == 0) ds4_phase1_vec(imgb, by, bx, y0, tmp);
        else               ds4_phase1_scalar(imgb, by, bx, y0, tmp);
        __syncthreads();

        const float4* t4 = (const float4*)tmp;   // ch stride 528, row stride 66
        int yy = tid >> 6, i = tid & 63;
        float* op = ob + (y0 + yy) * G + i;
        float es = (i == 0 || i == 63) ? EDGE_SCALE : 1.0f;
#pragma unroll
        for (int ch = 0; ch < 3; ch++) {
            float4 a = t4[ch * 528 + yy * 66 + i];
            float4 bb = t4[ch * 528 + yy * 66 + i + 1];
            float acc = (1.f/32)*a.x + (3.f/32)*a.y + (5.f/32)*a.z + (7.f/32)*a.w
                      + (7.f/32)*bb.x + (5.f/32)*bb.y + (3.f/32)*bb.z + (1.f/32)*bb.w;
            op[ch * (G * G)] = acc * es;
        }
    } else if (sel == 1) {
        const float* imgb = img2 + (size_t)b * 3 * CHSTRIDE;
        float* ob = out + (size_t)(b * 9 + 3) * (G * G);
        int by = sy - 64, bx = sx - 64, y0 = slice * 16;

        // zero pads: 48 rows (stride 132) x {0,129}
        if (tid < 96) {
            int rs = tid >> 1, k = tid & 1;
            tmp[rs * 132 + (k ? 129 : 0)] = 0.f;
        }
        if ((bx & 1) == 0) ds2_phase1_vec(imgb, by, bx, y0, tmp);
        else               ds2_phase1_scalar(imgb, by, bx, y0, tmp);
        __syncthreads();

        const float2* t2 = (const float2*)tmp;   // ch stride 1056, row stride 66
#pragma unroll
        for (int u = 0; u < 2; u++) {
            int idx = tid + u * NTHREADS;        // 16*64 = 1024
            int yy = idx >> 6, i = idx & 63;
            float* op = ob + (y0 + yy) * G + i;
            float es = (i == 0 || i == 63) ? EDGE_SCALE : 1.0f;
#pragma unroll
            for (int ch = 0; ch < 3; ch++) {
                float2 a = t2[ch * 1056 + yy * 66 + i];
                float2 bb = t2[ch * 1056 + yy * 66 + i + 1];
                float acc = (1.f/8)*a.x + (3.f/8)*a.y + (3.f/8)*bb.x + (1.f/8)*bb.y;
                op[ch * (G * G)] = acc * es;
            }
        }
    } else {
        const float* imgb = img0 + (size_t)b * 3 * CHSTRIDE;
        float* ob = out + (size_t)(b * 9 + 0) * (G * G);
        int by = sy - G / 2, bx = sx - G / 2;
#pragma unroll
        for (int u = 0; u < 8; u++) {
            int idx = tid + u * NTHREADS;   // 4096 positions
            int y = idx >> 6, x = idx & 63;
            int gy = by + y, gx = bx + x;
            bool ok = (unsigned)gy < IMGSZ && (unsigned)gx < IMGSZ;
            const float* q = imgb + (size_t)(ok ? gy : 0) * IMGSZ + (ok ? gx : 0);
#pragma unroll
            for (int ch = 0; ch < 3; ch++)
                ob[ch * (G * G) + y * G + x] = ok ? __ldg(q + ch * CHSTRIDE) : 0.f;
        }
    }
}

extern "C" void kernel_launch(void* const* d_in, const int* in_sizes, int n_in,
                              void* d_out, int out_size) {
    const float* img0 = (const float*)d_in[0];
    const float* img2 = (const float*)d_in[1];
    const float* img4 = (const float*)d_in[2];
    const float* loc  = (const float*)d_in[3];
    float* out = (float*)d_out;

    const size_t smem = 25344;   // 3 * 8 * 264 * 4 == 3 * 16 * 132 * 4
    cudaFuncSetAttribute(glimpse_kernel,
                         cudaFuncAttributeMaxDynamicSharedMemorySize, (int)smem);
    glimpse_kernel<<<832, NTHREADS, smem>>>(img0, img2, img4, loc, out);
}